// round 16
// baseline (speedup 1.0000x reference)
#include <cuda_runtime.h>
#include <cuda.h>
#include <cuda_bf16.h>
#include <cuda_fp8.h>
#include <cstdint>

// Problem constants
#define N_TOK   384
#define WDIM    512
#define EMB     1024
#define HDIM    1024
#define NSPAN   73920
#define MTILES  578
#define NSPAN_PAD (MTILES*128)
#define NB      8            // n-blocks of 128
#define GROUPS  18           // persistent groups over M
#define TPG     33           // tiles per group (18*33 >= 578)

// Arch gate
#if defined(__CUDA_ARCH__) && (__CUDA_ARCH__ >= 1000) && defined(__CUDA_ARCH_FEAT_SM103_ALL)
#define HAS_TCGEN05 1
#else
#define HAS_TCGEN05 0
#endif

#define H_SCALE   256.0f
#define H_INV     (1.0f/256.0f)
#define W_SCALE   64.0f
#define DESCALE   (1.0f/16384.0f)

// Scratch
__device__ float g_pref[(N_TOK + 1) * EMB];
__device__ __nv_bfloat16 g_Pb[(N_TOK + 1) * HDIM];
__device__ uint8_t g_h1f8[(size_t)NSPAN_PAD * HDIM];
__device__ uint8_t g_h2f8[(size_t)NSPAN_PAD * HDIM];
__device__ int   g_si[NSPAN_PAD];
__device__ int   g_sj[NSPAN_PAD];
__device__ float g_wf[3 * HDIM];
__device__ float g_part[(size_t)NB * NSPAN_PAD];
__device__ uint8_t g_Wt2f8[HDIM * HDIM];
__device__ uint8_t g_Ws1tf8[HDIM * HDIM];

__device__ __forceinline__ uint32_t pack_e4m3x2(float lo, float hi) {
    uint16_t h;
    asm("cvt.rn.satfinite.e4m3x2.f32 %0, %1, %2;" : "=h"(h) : "f"(hi), "f"(lo));
    return (uint32_t)h;
}
__device__ __forceinline__ float2 bf2_to_f2(uint32_t w) {
    __nv_bfloat162 h = *reinterpret_cast<__nv_bfloat162*>(&w);
    return __bfloat1622float2(h);
}

#if HAS_TCGEN05
__device__ __forceinline__ uint32_t smem_u32(const void* p) {
    uint32_t a;
    asm("{ .reg .u64 t; cvta.to.shared.u64 t, %1; cvt.u32.u64 %0, t; }" : "=r"(a) : "l"(p));
    return a;
}

#define MBAR_INIT(addr, cnt) \
    asm volatile("mbarrier.init.shared.b64 [%0], %1;" :: "r"(addr), "r"(cnt) : "memory")
#define MBAR_INVAL(addr) \
    asm volatile("mbarrier.inval.shared.b64 [%0];" :: "r"(addr) : "memory")
#define MBAR_EXPECT_TX(addr, bytes) \
    asm volatile("mbarrier.arrive.expect_tx.shared.b64 _, [%0], %1;" \
        :: "r"((uint32_t)(addr)), "r"((uint32_t)(bytes)) : "memory")
#define MBAR_ARRIVE(addr) \
    asm volatile("mbarrier.arrive.shared.b64 _, [%0];" :: "r"((uint32_t)(addr)) : "memory")

#define MBAR_WAIT_PARITY(addr, parity) do {                                        \
    uint32_t _m = (addr); uint32_t _p = (parity); uint32_t _done;                  \
    asm volatile("{\n\t.reg .pred p;\n\t"                                          \
        "mbarrier.try_wait.parity.acquire.cta.shared::cta.b64 p, [%1], %2;\n\t"    \
        "selp.b32 %0, 1, 0, p;\n\t}"                                               \
        : "=r"(_done) : "r"(_m), "r"(_p) : "memory");                              \
    if (!_done) {                                                                  \
        asm volatile("{\n\t.reg .pred P1;\n\t"                                     \
            "WL_%=:\n\t"                                                           \
            "mbarrier.try_wait.parity.acquire.cta.shared::cta.b64 P1, [%0], %1, 0x989680;\n\t" \
            "@P1 bra.uni WD_%=;\n\t"                                               \
            "bra.uni WL_%=;\n\t"                                                   \
            "WD_%=:\n\t}"                                                          \
            :: "r"(_m), "r"(_p) : "memory");                                       \
    }                                                                              \
} while (0)

#define TMA_LOAD_2D(smem, tm, x, y, mbar) \
    asm volatile("cp.async.bulk.tensor.2d.shared::cta.global.tile.mbarrier::complete_tx::bytes " \
        "[%0], [%1, {%2, %3}], [%4];" \
        :: "r"((uint32_t)(smem)), "l"(tm), "r"((int)(x)), "r"((int)(y)), \
           "r"((uint32_t)(mbar)) : "memory")

#define TC_ALLOC(smem_addr, ncols) \
    asm volatile("tcgen05.alloc.cta_group::1.sync.aligned.shared::cta.b32 [%0], %1;" \
        :: "r"((uint32_t)(smem_addr)), "r"((uint32_t)(ncols)) : "memory")
#define TC_DEALLOC(tmem, ncols) \
    asm volatile("tcgen05.dealloc.cta_group::1.sync.aligned.b32 %0, %1;" \
        :: "r"(tmem), "r"((uint32_t)(ncols)))
#define TC_RELINQ() \
    asm volatile("tcgen05.relinquish_alloc_permit.cta_group::1.sync.aligned;")
#define TC_COMMIT(mbar) \
    asm volatile("tcgen05.commit.cta_group::1.mbarrier::arrive::one.shared::cluster.b64 [%0];" \
        :: "r"((uint32_t)(mbar)) : "memory")
#define TC_FENCE_BEFORE() asm volatile("tcgen05.fence::before_thread_sync;" ::: "memory")
#define TC_FENCE_AFTER()  asm volatile("tcgen05.fence::after_thread_sync;" ::: "memory")
#define TC_WAIT_LD()      asm volatile("tcgen05.wait::ld.sync.aligned;" ::: "memory")

#define TC_LD_X32(r, tmem_addr) \
    asm volatile("tcgen05.ld.sync.aligned.32x32b.x32.b32 " \
        "{%0, %1, %2, %3, %4, %5, %6, %7, %8, %9, %10, %11, %12, %13, %14, %15, " \
        " %16, %17, %18, %19, %20, %21, %22, %23, %24, %25, %26, %27, %28, %29, %30, %31}, [%32];" \
        : "=r"((r)[0]),  "=r"((r)[1]),  "=r"((r)[2]),  "=r"((r)[3]), \
          "=r"((r)[4]),  "=r"((r)[5]),  "=r"((r)[6]),  "=r"((r)[7]), \
          "=r"((r)[8]),  "=r"((r)[9]),  "=r"((r)[10]), "=r"((r)[11]), \
          "=r"((r)[12]), "=r"((r)[13]), "=r"((r)[14]), "=r"((r)[15]), \
          "=r"((r)[16]), "=r"((r)[17]), "=r"((r)[18]), "=r"((r)[19]), \
          "=r"((r)[20]), "=r"((r)[21]), "=r"((r)[22]), "=r"((r)[23]), \
          "=r"((r)[24]), "=r"((r)[25]), "=r"((r)[26]), "=r"((r)[27]), \
          "=r"((r)[28]), "=r"((r)[29]), "=r"((r)[30]), "=r"((r)[31]) \
        : "r"(tmem_addr))

static constexpr uint64_t DESC_BASE_SW128 =
    (uint64_t(2) << 61) | (uint64_t(1) << 46) | (uint64_t(64) << 32) | (uint64_t(1) << 16);
__device__ __forceinline__ uint64_t make_desc(uint32_t addr) {
    return DESC_BASE_SW128 | ((uint64_t)(addr >> 4) & 0x3FFF);
}

__device__ __forceinline__ void mma_f8_ss(uint32_t d, uint64_t ad, uint64_t bd,
                                          uint32_t idesc, bool acc) {
    uint32_t en = acc ? 1u : 0u;
    asm volatile(
        "{\n\t.reg .pred p;\n\t"
        "setp.ne.u32 p, %4, 0;\n\t"
        "tcgen05.mma.cta_group::1.kind::f8f6f4 [%0], %1, %2, %3, {%5, %5, %5, %5}, p;\n\t"
        "}"
        :: "r"(d), "l"(ad), "l"(bd), "r"(idesc), "r"(en), "r"(0u)
        : "memory");
}
// dtype=F32, E4M3, N=128, M=128
#define IDESC_F8 ((1u<<4)|(16u<<17)|(8u<<24))
#endif  // HAS_TCGEN05

// ---------------------------------------------------------------------------
// k_pre: fused pref / spans / wfeat
// ---------------------------------------------------------------------------
__global__ __launch_bounds__(256) void k_pre(
    const int* __restrict__ sent, const int* __restrict__ pos,
    const float* __restrict__ We_wrd, const float* __restrict__ We_pos,
    const float* __restrict__ W_s1)
{
    int bx = blockIdx.x;
    int tid = threadIdx.x;
    if (bx < N_TOK) {
        int i = bx;
        int base = i * N_TOK - (i * (i - 1)) / 2;
        for (int j = i + tid; j < N_TOK; j += 256) {
            int s = base + (j - i);
            g_si[s] = i;
            g_sj[s] = j;
        }
        if (bx == 0) {
            for (int s = NSPAN + tid; s < NSPAN_PAD; s += 256) {
                g_si[s] = 0; g_sj[s] = 0;
            }
        }
    } else if (bx < N_TOK + 4) {
        int c = (bx - N_TOK) * 256 + tid;
        bool isPos = (c < WDIM);
        const float* base = isPos ? (We_pos + c) : (We_wrd + (c - WDIM));
        const int*   idx  = isPos ? pos : sent;
        float run = 0.f;
        g_pref[c] = 0.f;
        #pragma unroll 4
        for (int t = 0; t < N_TOK; ++t) {
            run += base[(size_t)idx[t] * WDIM];
            g_pref[(t + 1) * EMB + c] = run;
        }
    } else {
        int n = (bx - N_TOK - 4) * 256 + tid;
        float sl = 0.f, si = 0.f, se = 0.f;
        #pragma unroll
        for (int r = 0; r < 16; ++r) {
            sl += W_s1[(HDIM +      r) * HDIM + n];
            si += W_s1[(HDIM + 16 + r) * HDIM + n];
            se += W_s1[(HDIM + 32 + r) * HDIM + n];
        }
        g_wf[n] = sl; g_wf[HDIM + n] = si; g_wf[2 * HDIM + n] = se;
    }
}

// ---------------------------------------------------------------------------
// k_gemmP: P = pref @ W_dan1  (64x64 tiles, 4x4/thread) fp32 -> bf16
// ---------------------------------------------------------------------------
__global__ __launch_bounds__(256) void k_gemmP(const float* __restrict__ W)
{
    __shared__ float As[64][17];
    __shared__ float Bs[16][68];
    int tid = threadIdx.x;
    int tx = tid % 16, ty = tid / 16;
    int m0 = blockIdx.x * 64, n0 = blockIdx.y * 64;
    float acc[4][4] = {};

    for (int kk = 0; kk < EMB; kk += 16) {
        #pragma unroll
        for (int e = tid; e < 64 * 16; e += 256) {
            int r = e >> 4, c = e & 15;
            int gm = m0 + r;
            As[r][c] = (gm <= N_TOK) ? g_pref[gm * EMB + kk + c] : 0.f;
        }
        #pragma unroll
        for (int e = tid; e < 16 * 64; e += 256) {
            int r = e >> 6, c = e & 63;
            Bs[r][c] = W[(kk + r) * HDIM + n0 + c];
        }
        __syncthreads();
        #pragma unroll
        for (int k = 0; k < 16; ++k) {
            float a[4], b[4];
            #pragma unroll
            for (int q = 0; q < 4; ++q) { a[q] = As[ty * 4 + q][k]; b[q] = Bs[k][tx * 4 + q]; }
            #pragma unroll
            for (int i = 0; i < 4; ++i)
                #pragma unroll
                for (int j = 0; j < 4; ++j)
                    acc[i][j] = fmaf(a[i], b[j], acc[i][j]);
        }
        __syncthreads();
    }
    #pragma unroll
    for (int i = 0; i < 4; ++i) {
        int gm = m0 + ty * 4 + i;
        if (gm <= N_TOK)
            #pragma unroll
            for (int j = 0; j < 4; ++j)
                g_Pb[gm * HDIM + n0 + tx * 4 + j] = __float2bfloat16(acc[i][j]);
    }
}

// ---------------------------------------------------------------------------
// k_mid: h1 materialization (e4m3 x2^8, bf16 P reads) + weight transposes
// ---------------------------------------------------------------------------
__device__ __forceinline__ void transp_body(const float* __restrict__ src,
                                            uint8_t* __restrict__ dst, int q, int tid)
{
    __shared__ float t[32][33];
    int tx = tid & 31, ty = tid >> 5;
    int bx = q & 31, by = q >> 5;
    int x = bx * 32 + tx;
    int y = by * 32 + ty;
    #pragma unroll
    for (int j = 0; j < 32; j += 8)
        t[ty + j][tx] = src[(size_t)(y + j) * HDIM + x];
    __syncthreads();
    x = by * 32 + tx;
    y = bx * 32 + ty;
    #pragma unroll
    for (int j = 0; j < 32; j += 8) {
        __nv_fp8_e4m3 v(t[tx][ty + j] * W_SCALE);
        dst[(size_t)(y + j) * HDIM + x] = *reinterpret_cast<uint8_t*>(&v);
    }
}

__global__ __launch_bounds__(256) void k_mid(const float* __restrict__ b_dan1,
                                             const float* __restrict__ W_dan2,
                                             const float* __restrict__ W_s1)
{
    int bx = blockIdx.x;
    int tid = threadIdx.x;
    if (bx < NSPAN_PAD / 16) {
        int s = bx * 16 + (tid >> 4);
        int sc = (s < NSPAN) ? s : (NSPAN - 1);
        int i_ = g_si[sc], j_ = g_sj[sc];
        float inv = 1.0f / (float)(j_ - i_ + 1);
        const __nv_bfloat16* pe = g_Pb + (size_t)(j_ + 1) * HDIM;
        const __nv_bfloat16* pi = g_Pb + (size_t)i_ * HDIM;
        int cg = (tid & 15) * 64;
        uint8_t* orow = g_h1f8 + (size_t)s * HDIM + cg;
        #pragma unroll
        for (int q = 0; q < 64; q += 16) {
            uint4 e0 = *(const uint4*)(pe + cg + q);
            uint4 e1 = *(const uint4*)(pe + cg + q + 8);
            uint4 i0 = *(const uint4*)(pi + cg + q);
            uint4 i1 = *(const uint4*)(pi + cg + q + 8);
            uint32_t ew[8] = {e0.x, e0.y, e0.z, e0.w, e1.x, e1.y, e1.z, e1.w};
            uint32_t iw[8] = {i0.x, i0.y, i0.z, i0.w, i1.x, i1.y, i1.z, i1.w};
            uint32_t w[4];
            #pragma unroll
            for (int g = 0; g < 4; ++g) {
                float2 ea = bf2_to_f2(ew[g * 2]);
                float2 eb = bf2_to_f2(ew[g * 2 + 1]);
                float2 ia = bf2_to_f2(iw[g * 2]);
                float2 ib = bf2_to_f2(iw[g * 2 + 1]);
                float4 b4 = *(const float4*)(b_dan1 + cg + q + g * 4);
                float v0 = fmaxf(fmaf(ea.x - ia.x, inv, b4.x), 0.f) * H_SCALE;
                float v1 = fmaxf(fmaf(ea.y - ia.y, inv, b4.y), 0.f) * H_SCALE;
                float v2 = fmaxf(fmaf(eb.x - ib.x, inv, b4.z), 0.f) * H_SCALE;
                float v3 = fmaxf(fmaf(eb.y - ib.y, inv, b4.w), 0.f) * H_SCALE;
                w[g] = pack_e4m3x2(v0, v1) | (pack_e4m3x2(v2, v3) << 16);
            }
            uint4 o; o.x = w[0]; o.y = w[1]; o.z = w[2]; o.w = w[3];
            *(uint4*)(orow + q) = o;
        }
    } else if (bx < NSPAN_PAD / 16 + 1024) {
        transp_body(W_dan2, g_Wt2f8, bx - NSPAN_PAD / 16, tid);
    } else {
        transp_body(W_s1, g_Ws1tf8, bx - NSPAN_PAD / 16 - 1024, tid);
    }
}

// ---------------------------------------------------------------------------
// Persistent GEMM (fp8 tcgen05 + TMA): grid (NB, GROUPS), 1 CTA/SM.
// B panel (128 x 1024 fp8 = 128KB) SMEM-resident; A: 4-stage TMA ring (4x16KB).
// TMEM: D 4-buffer (4 x 128 cols). Split producer: thread 0 = MMA issuer,
// thread 32 = TMA issuer. Epilogue: warps 4-7, overlapped via dready/dfree.
// ---------------------------------------------------------------------------
template <int MODE>
__global__ __launch_bounds__(256, 1)
void k_gemm_big(const __grid_constant__ CUtensorMap tmA,
                const __grid_constant__ CUtensorMap tmB,
                const float* __restrict__ W,          // fp32 [K][N] (fallback)
                const float* __restrict__ bias2,      // b_dan2 / b_s1
                const float* __restrict__ Ws2)        // MODE 3
{
#if HAS_TCGEN05
    extern __shared__ __align__(1024) char dyn[];
    // A ring 4 x 16KB @ 0..64K ; B panel 8 x 16KB @ 64K..192K
    char* sB = dyn + 65536;

    __shared__ float sepi[5 * 128];
    __shared__ __align__(8) unsigned long long s_mbar[17]; // afull[4] afree[4] dready[4] dfree[4] bbar
    __shared__ uint32_t s_tmemptr;

    const int tid = threadIdx.x;
    const int nx = blockIdx.x;
    const int n0 = nx * 128;
    const int base = blockIdx.y * TPG;
    const int nt = min(TPG, MTILES - base);

    if (tid == 0) {
        #pragma unroll
        for (int q = 0; q < 4; ++q)  MBAR_INIT(smem_u32(&s_mbar[q]), 1);       // afull
        #pragma unroll
        for (int q = 4; q < 8; ++q)  MBAR_INIT(smem_u32(&s_mbar[q]), 1);       // afree
        #pragma unroll
        for (int q = 8; q < 12; ++q) MBAR_INIT(smem_u32(&s_mbar[q]), 1);       // dready
        #pragma unroll
        for (int q = 12; q < 16; ++q) MBAR_INIT(smem_u32(&s_mbar[q]), 4);      // dfree (4 warps)
        MBAR_INIT(smem_u32(&s_mbar[16]), 1);                                    // bbar
    }
    if (tid < 128) {
        sepi[tid] = bias2[n0 + tid];
        if (MODE == 3) {
            sepi[128 + tid] = g_wf[n0 + tid];
            sepi[256 + tid] = g_wf[HDIM + n0 + tid];
            sepi[384 + tid] = g_wf[2 * HDIM + n0 + tid];
            sepi[512 + tid] = Ws2[n0 + tid];
        }
    }
    __syncthreads();

    if (tid < 32) {
        TC_ALLOC(smem_u32(&s_tmemptr), 512);
        TC_RELINQ();
    }
    __syncthreads();
    const uint32_t tmem = s_tmemptr;
    const int G = nt * 8;

    if (tid == 0) {
        // ================= MMA issuer =================
        uint32_t afull[4], afree[4];
        #pragma unroll
        for (int q = 0; q < 4; ++q) { afull[q] = smem_u32(&s_mbar[q]); afree[q] = smem_u32(&s_mbar[4 + q]); }
        const uint32_t dready[4] = { smem_u32(&s_mbar[8]),  smem_u32(&s_mbar[9]),
                                     smem_u32(&s_mbar[10]), smem_u32(&s_mbar[11]) };
        const uint32_t dfree[4]  = { smem_u32(&s_mbar[12]), smem_u32(&s_mbar[13]),
                                     smem_u32(&s_mbar[14]), smem_u32(&s_mbar[15]) };
        uint64_t adesc[4], bdesc[8];
        #pragma unroll
        for (int q = 0; q < 4; ++q) adesc[q] = make_desc(smem_u32(dyn + q * 16384));
        #pragma unroll
        for (int q = 0; q < 8; ++q) bdesc[q] = make_desc(smem_u32(sB + q * 16384));

        MBAR_WAIT_PARITY(smem_u32(&s_mbar[16]), 0);   // B panel resident

        int aph[4] = {0,0,0,0}, dph[4] = {0,0,0,0};
        #pragma unroll 1
        for (int g = 0; g < G; ++g) {
            const int s = g & 3, c = g & 7, t = g >> 3, d = t & 3;
            MBAR_WAIT_PARITY(afull[s], aph[s]); aph[s] ^= 1;
            if (c == 0 && t >= 4) { MBAR_WAIT_PARITY(dfree[d], dph[d]); dph[d] ^= 1; }
            #pragma unroll
            for (int k = 0; k < 4; ++k)
                mma_f8_ss(tmem + d * 128, adesc[s] + k * 2, bdesc[c] + k * 2, IDESC_F8,
                          !(c == 0 && k == 0));
            TC_COMMIT(afree[s]);
            if (c == 7) TC_COMMIT(dready[d]);
        }
    } else if (tid == 32) {
        // ================= TMA issuer =================
        uint32_t afull[4], afree[4];
        #pragma unroll
        for (int q = 0; q < 4; ++q) { afull[q] = smem_u32(&s_mbar[q]); afree[q] = smem_u32(&s_mbar[4 + q]); }
        const uint32_t bbar = smem_u32(&s_mbar[16]);

        // B panel (8 x 16KB)
        MBAR_EXPECT_TX(bbar, 131072);
        #pragma unroll
        for (int c = 0; c < 8; ++c)
            TMA_LOAD_2D(smem_u32(sB + c * 16384), &tmB, c * 128, n0, bbar);

        // A prologue: chunks 0..3
        #pragma unroll
        for (int g = 0; g < 4; ++g) {
            if (g < G) {
                MBAR_EXPECT_TX(afull[g], 16384);
                TMA_LOAD_2D(smem_u32(dyn + g * 16384), &tmA,
                            (g & 7) * 128, (base + (g >> 3)) * 128, afull[g]);
            }
        }
        // steady state: chunk g gated on MMA completion of chunk g-4 (same stage)
        int frph[4] = {0,0,0,0};
        #pragma unroll 1
        for (int g = 4; g < G; ++g) {
            const int s = g & 3;
            MBAR_WAIT_PARITY(afree[s], frph[s]); frph[s] ^= 1;
            MBAR_EXPECT_TX(afull[s], 16384);
            TMA_LOAD_2D(smem_u32(dyn + s * 16384), &tmA,
                        (g & 7) * 128, (base + (g >> 3)) * 128, afull[s]);
        }
    } else if (tid >= 128) {
        // ================= epilogue: warps 4-7 =================
        const uint32_t dready[4] = { smem_u32(&s_mbar[8]),  smem_u32(&s_mbar[9]),
                                     smem_u32(&s_mbar[10]), smem_u32(&s_mbar[11]) };
        const uint32_t dfree[4]  = { smem_u32(&s_mbar[12]), smem_u32(&s_mbar[13]),
                                     smem_u32(&s_mbar[14]), smem_u32(&s_mbar[15]) };
        const int rt = tid - 128;
        int eph[4] = {0,0,0,0};
        #pragma unroll 1
        for (int t = 0; t < nt; ++t) {
            const int d = t & 3;
            const int gs = (base + t) * 128 + rt;
            MBAR_WAIT_PARITY(dready[d], eph[d]); eph[d] ^= 1;
            TC_FENCE_AFTER();
            if (MODE == 2) {
                bool ok = gs < NSPAN;
                uint8_t* orow = g_h2f8 + (size_t)(ok ? gs : 0) * HDIM + n0;
                #pragma unroll 1
                for (int nb = 0; nb < 4; ++nb) {
                    uint32_t r[32];
                    TC_LD_X32(r, tmem + d * 128 + nb * 32);
                    TC_WAIT_LD();
                    if (ok) {
                        int cb0 = nb * 32;
                        uint32_t w[8];
                        #pragma unroll
                        for (int q = 0; q < 32; q += 4) {
                            float a0 = fmaxf(fmaf(__uint_as_float(r[q + 0]), DESCALE, sepi[cb0 + q + 0]), 0.f) * H_SCALE;
                            float a1 = fmaxf(fmaf(__uint_as_float(r[q + 1]), DESCALE, sepi[cb0 + q + 1]), 0.f) * H_SCALE;
                            float a2 = fmaxf(fmaf(__uint_as_float(r[q + 2]), DESCALE, sepi[cb0 + q + 2]), 0.f) * H_SCALE;
                            float a3 = fmaxf(fmaf(__uint_as_float(r[q + 3]), DESCALE, sepi[cb0 + q + 3]), 0.f) * H_SCALE;
                            w[q >> 2] = pack_e4m3x2(a0, a1) | (pack_e4m3x2(a2, a3) << 16);
                        }
                        uint4 o;
                        o.x = w[0]; o.y = w[1]; o.z = w[2]; o.w = w[3];
                        *(uint4*)(orow + nb * 32) = o;
                        o.x = w[4]; o.y = w[5]; o.z = w[6]; o.w = w[7];
                        *(uint4*)(orow + nb * 32 + 16) = o;
                    }
                }
            } else {
                int sc = (gs < NSPAN) ? gs : (NSPAN - 1);
                int i_ = g_si[sc], j_ = g_sj[sc];
                float fl = (float)(j_ - i_ + 1);
                float fi = (float)i_;
                float fe = (float)(j_ + 1);
                float sum = 0.f;
                #pragma unroll 1
                for (int nb = 0; nb < 4; ++nb) {
                    uint32_t r[32];
                    TC_LD_X32(r, tmem + d * 128 + nb * 32);
                    TC_WAIT_LD();
                    #pragma unroll
                    for (int q = 0; q < 32; ++q) {
                        int n = nb * 32 + q;
                        float v = fmaf(__uint_as_float(r[q]), DESCALE, sepi[n]);
                        v = fmaf(fl, sepi[128 + n], v);
                        v = fmaf(fi, sepi[256 + n], v);
                        v = fmaf(fe, sepi[384 + n], v);
                        v = fmaxf(v, 0.f);
                        sum = fmaf(v, sepi[512 + n], sum);
                    }
                }
                g_part[(size_t)nx * NSPAN_PAD + gs] = sum;
            }
            TC_FENCE_BEFORE();
            if ((tid & 31) == 0) MBAR_ARRIVE(dfree[d]);
        }
    }

    __syncthreads();
    if (tid == 0) {
        #pragma unroll
        for (int q = 0; q < 17; ++q) MBAR_INVAL(smem_u32(&s_mbar[q]));
    }
    __syncthreads();
    if (tid < 32) TC_DEALLOC(tmem, 512);

#else
    // ======================= SIMT fp32 fallback (persistent, N=128) ============
    __shared__ __align__(16) float sh[2304];
    float* As = sh;
    float* Bs = sh + 1024;

    int tid = threadIdx.x;
    int tx = tid % 16, ty = tid / 16;
    const int nx = blockIdx.x;
    const int n0 = nx * 128;
    const int base = blockIdx.y * TPG;
    const int nt = min(TPG, MTILES - base);
    const uint8_t* Af8 = (MODE == 2) ? g_h1f8 : g_h2f8;

    int lm = tid >> 1, lkh = tid & 1;
    int br = tid >> 5;
    int bc = (tid & 31) << 2;

    #pragma unroll 1
    for (int t = 0; t < nt; ++t) {
        int m0 = (base + t) * 128;
        int sA_ = m0 + lm; if (sA_ >= NSPAN) sA_ = NSPAN - 1;

        float acc[8][8];
        #pragma unroll
        for (int a = 0; a < 8; ++a)
            #pragma unroll
            for (int b = 0; b < 8; ++b) acc[a][b] = 0.f;

        for (int kk = 0; kk < HDIM; kk += 8) {
            const uint8_t* ar = Af8 + (size_t)sA_ * HDIM + kk + lkh * 4;
            #pragma unroll
            for (int q = 0; q < 4; ++q) {
                __nv_fp8_e4m3 f8 = *reinterpret_cast<const __nv_fp8_e4m3*>(ar + q);
                As[(lkh * 4 + q) * 128 + lm] = float(f8) * H_INV;
            }
            *(float4*)(Bs + br * 128 + bc) = *(const float4*)(W + (size_t)(kk + br) * HDIM + n0 + bc);
            __syncthreads();

            #pragma unroll
            for (int k = 0; k < 8; ++k) {
                float a[8], b[8];
                float4 v;
                v = *(const float4*)(As + k * 128 + (ty << 2));      a[0]=v.x; a[1]=v.y; a[2]=v.z; a[3]=v.w;
                v = *(const float4*)(As + k * 128 + (ty << 2) + 64); a[4]=v.x; a[5]=v.y; a[6]=v.z; a[7]=v.w;
                v = *(const float4*)(Bs + k * 128 + (tx << 2));      b[0]=v.x; b[1]=v.y; b[2]=v.z; b[3]=v.w;
                v = *(const float4*)(Bs + k * 128 + (tx << 2) + 64); b[4]=v.x; b[5]=v.y; b[6]=v.z; b[7]=v.w;
                #pragma unroll
                for (int ii = 0; ii < 8; ++ii)
                    #pragma unroll
                    for (int jj = 0; jj < 8; ++jj)
                        acc[ii][jj] = fmaf(a[ii], b[jj], acc[ii][jj]);
            }
            __syncthreads();
        }

        if (MODE == 2) {
            float cb[8];
            #pragma unroll
            for (int q = 0; q < 4; ++q) {
                cb[q]     = bias2[n0 + (tx << 2) + q];
                cb[4 + q] = bias2[n0 + (tx << 2) + 64 + q];
            }
            #pragma unroll
            for (int ri = 0; ri < 8; ++ri) {
                int r = (ri < 4) ? ((ty << 2) + ri) : (64 + (ty << 2) + ri - 4);
                int gs = m0 + r;
                if (gs < NSPAN) {
                    #pragma unroll
                    for (int q = 0; q < 4; ++q) {
                        __nv_fp8_e4m3 v0(fmaxf(acc[ri][q] + cb[q], 0.f) * H_SCALE);
                        __nv_fp8_e4m3 v1(fmaxf(acc[ri][4 + q] + cb[4 + q], 0.f) * H_SCALE);
                        g_h2f8[(size_t)gs * HDIM + n0 + (tx << 2) + q]      = *reinterpret_cast<uint8_t*>(&v0);
                        g_h2f8[(size_t)gs * HDIM + n0 + (tx << 2) + 64 + q] = *reinterpret_cast<uint8_t*>(&v1);
                    }
                }
            }
        } else {
            int cbase = n0 + (tx << 2);
            float cb[8], cl[8], ci[8], ce[8], cw[8];
            #pragma unroll
            for (int q = 0; q < 4; ++q) {
                int c0 = cbase + q, c1 = cbase + 64 + q;
                cb[q] = bias2[c0];             cb[4+q] = bias2[c1];
                cl[q] = g_wf[c0];              cl[4+q] = g_wf[c1];
                ci[q] = g_wf[HDIM + c0];       ci[4+q] = g_wf[HDIM + c1];
                ce[q] = g_wf[2*HDIM + c0];     ce[4+q] = g_wf[2*HDIM + c1];
                cw[q] = Ws2[c0];               cw[4+q] = Ws2[c1];
            }
            float rs[8];
            #pragma unroll
            for (int ri = 0; ri < 8; ++ri) {
                int r = (ri < 4) ? ((ty << 2) + ri) : (64 + (ty << 2) + ri - 4);
                int gs = m0 + r; int sc = (gs < NSPAN) ? gs : (NSPAN - 1);
                int ii_ = g_si[sc], jj_ = g_sj[sc];
                float fl = (float)(jj_ - ii_ + 1);
                float fi = (float)ii_;
                float fe = (float)(jj_ + 1);
                float sum = 0.f;
                #pragma unroll
                for (int cc = 0; cc < 8; ++cc) {
                    float v = acc[ri][cc] + cb[cc];
                    v = fmaf(fl, cl[cc], v);
                    v = fmaf(fi, ci[cc], v);
                    v = fmaf(fe, ce[cc], v);
                    v = fmaxf(v, 0.f);
                    sum = fmaf(v, cw[cc], sum);
                }
                rs[ri] = sum;
            }
            #pragma unroll
            for (int ri = 0; ri < 8; ++ri) {
                int r = (ri < 4) ? ((ty << 2) + ri) : (64 + (ty << 2) + ri - 4);
                sh[r * 17 + tx] = rs[ri];
            }
            __syncthreads();
            if (tid < 128) {
                float v = 0.f;
                #pragma unroll
                for (int q = 0; q < 16; ++q) v += sh[tid * 17 + q];
                g_part[(size_t)nx * NSPAN_PAD + m0 + tid] = v;
            }
            __syncthreads();
        }
    }
#endif
}

// ---------------------------------------------------------------------------
// Final reduce (NB column-block partials)
// ---------------------------------------------------------------------------
__global__ void k_final(const float* __restrict__ b_s2, float* __restrict__ out)
{
    int s = blockIdx.x * blockDim.x + threadIdx.x;
    if (s < NSPAN) {
        float t = b_s2[0];
        #pragma unroll
        for (int q = 0; q < NB; ++q) t += g_part[(size_t)q * NSPAN_PAD + s];
        out[s] = t;
    }
}

// ---------------------------------------------------------------------------
// Host: tensor maps
// ---------------------------------------------------------------------------
typedef CUresult (*tm_encode_fn)(
    CUtensorMap*, CUtensorMapDataType, cuuint32_t, void*,
    const cuuint64_t*, const cuuint64_t*, const cuuint32_t*, const cuuint32_t*,
    CUtensorMapInterleave, CUtensorMapSwizzle, CUtensorMapL2promotion,
    CUtensorMapFloatOOBfill);

static tm_encode_fn get_encoder()
{
    static tm_encode_fn fn = nullptr;
    if (!fn) {
        cudaDriverEntryPointQueryResult st;
        void* p = nullptr;
        cudaGetDriverEntryPointByVersion("cuTensorMapEncodeTiled", &p, 12000,
                                         cudaEnableDefault, &st);
        fn = (tm_encode_fn)p;
    }
    return fn;
}

static void make_tm_2d(CUtensorMap* tm, void* base, uint64_t rows, uint32_t box_rows)
{
    cuuint64_t dims[2]    = { (cuuint64_t)HDIM, (cuuint64_t)rows };
    cuuint64_t strides[1] = { (cuuint64_t)HDIM };
    cuuint32_t box[2]     = { 128u, box_rows };
    cuuint32_t es[2]      = { 1u, 1u };
    get_encoder()(tm, CU_TENSOR_MAP_DATA_TYPE_UINT8, 2, base,
                  dims, strides, box, es,
                  CU_TENSOR_MAP_INTERLEAVE_NONE, CU_TENSOR_MAP_SWIZZLE_128B,
                  CU_TENSOR_MAP_L2_PROMOTION_L2_128B,
                  CU_TENSOR_MAP_FLOAT_OOB_FILL_NONE);
}

extern "C" void kernel_launch(void* const* d_in, const int* in_sizes, int n_in,
                              void* d_out, int out_size)
{
    const int*   sent    = (const int*)d_in[0];
    const int*   pos     = (const int*)d_in[1];
    const float* We_wrd  = (const float*)d_in[2];
    const float* We_pos  = (const float*)d_in[3];
    const float* W_dan1  = (const float*)d_in[4];
    const float* b_dan1  = (const float*)d_in[5];
    const float* W_dan2  = (const float*)d_in[6];
    const float* b_dan2  = (const float*)d_in[7];
    const float* W_s1    = (const float*)d_in[8];
    const float* b_s1    = (const float*)d_in[9];
    const float* W_s2    = (const float*)d_in[10];
    const float* b_s2    = (const float*)d_in[11];
    float* out = (float*)d_out;

    static bool init_done = false;
    static CUtensorMap tmA2, tmB2, tmA3, tmB3;
    if (!init_done) {
        cudaFuncSetAttribute((const void*)k_gemm_big<2>,
                             cudaFuncAttributeMaxDynamicSharedMemorySize, 196608);
        cudaFuncSetAttribute((const void*)k_gemm_big<3>,
                             cudaFuncAttributeMaxDynamicSharedMemorySize, 196608);
        void *h1p, *h2p, *wt2p, *ws1p;
        cudaGetSymbolAddress(&h1p,  g_h1f8);
        cudaGetSymbolAddress(&h2p,  g_h2f8);
        cudaGetSymbolAddress(&wt2p, g_Wt2f8);
        cudaGetSymbolAddress(&ws1p, g_Ws1tf8);
        make_tm_2d(&tmA2, h1p,  NSPAN_PAD, 128);
        make_tm_2d(&tmA3, h2p,  NSPAN_PAD, 128);
        make_tm_2d(&tmB2, wt2p, HDIM,      128);
        make_tm_2d(&tmB3, ws1p, HDIM,      128);
        init_done = true;
    }

    k_pre  <<<N_TOK + 8, 256>>>(sent, pos, We_wrd, We_pos, W_s1);          // 0
    k_gemmP<<<dim3(7, 16), 256>>>(W_dan1);                                  // 1
    k_mid  <<<NSPAN_PAD / 16 + 2048, 256>>>(b_dan1, W_dan2, W_s1);          // 2
    k_gemm_big<2><<<dim3(NB, GROUPS), 256, 196608>>>(tmA2, tmB2, W_dan2, b_dan2, nullptr); // 3 (ncu slot)
    k_gemm_big<3><<<dim3(NB, GROUPS), 256, 196608>>>(tmA3, tmB3, W_s1,   b_s1,  W_s2);     // 4
    k_final<<<(NSPAN + 255) / 256, 256>>>(b_s2, out);                       // 5
}

// round 17
// speedup vs baseline: 1.1602x; 1.1602x over previous
#include <cuda_runtime.h>
#include <cuda.h>
#include <cuda_bf16.h>
#include <cuda_fp8.h>
#include <cstdint>

// Problem constants
#define N_TOK   384
#define WDIM    512
#define EMB     1024
#define HDIM    1024
#define NSPAN   73920
#define MTILES  578
#define NSPAN_PAD (MTILES*128)

// Arch gate
#if defined(__CUDA_ARCH__) && (__CUDA_ARCH__ >= 1000) && defined(__CUDA_ARCH_FEAT_SM103_ALL)
#define HAS_TCGEN05 1
#else
#define HAS_TCGEN05 0
#endif

#define H_SCALE   256.0f
#define H_INV     (1.0f/256.0f)
#define W_SCALE   64.0f
#define DESCALE   (1.0f/16384.0f)

// Scratch
__device__ float g_pref[(N_TOK + 1) * EMB];
__device__ __nv_bfloat16 g_Pb[(N_TOK + 1) * HDIM];
__device__ uint8_t g_h1f8[(size_t)NSPAN_PAD * HDIM];
__device__ uint8_t g_h2f8[(size_t)NSPAN_PAD * HDIM];
__device__ int   g_si[NSPAN_PAD];
__device__ int   g_sj[NSPAN_PAD];
__device__ float g_wf[3 * HDIM];
__device__ float g_part[(size_t)4 * NSPAN_PAD];
__device__ uint8_t g_Wt2f8[HDIM * HDIM];
__device__ uint8_t g_Ws1tf8[HDIM * HDIM];

__device__ __forceinline__ uint32_t pack_e4m3x2(float lo, float hi) {
    uint16_t h;
    asm("cvt.rn.satfinite.e4m3x2.f32 %0, %1, %2;" : "=h"(h) : "f"(hi), "f"(lo));
    return (uint32_t)h;
}
__device__ __forceinline__ float2 bf2_to_f2(uint32_t w) {
    __nv_bfloat162 h = *reinterpret_cast<__nv_bfloat162*>(&w);
    return __bfloat1622float2(h);
}

#if HAS_TCGEN05
__device__ __forceinline__ uint32_t smem_u32(const void* p) {
    uint32_t a;
    asm("{ .reg .u64 t; cvta.to.shared.u64 t, %1; cvt.u32.u64 %0, t; }" : "=r"(a) : "l"(p));
    return a;
}

#define MBAR_INIT(addr, cnt) \
    asm volatile("mbarrier.init.shared.b64 [%0], %1;" :: "r"(addr), "r"(cnt) : "memory")
#define MBAR_INVAL(addr) \
    asm volatile("mbarrier.inval.shared.b64 [%0];" :: "r"(addr) : "memory")
#define MBAR_EXPECT_TX(addr, bytes) \
    asm volatile("mbarrier.arrive.expect_tx.shared.b64 _, [%0], %1;" \
        :: "r"((uint32_t)(addr)), "r"((uint32_t)(bytes)) : "memory")

#define MBAR_WAIT_PARITY(addr, parity) do {                                        \
    uint32_t _m = (addr); uint32_t _p = (parity); uint32_t _done;                  \
    asm volatile("{\n\t.reg .pred p;\n\t"                                          \
        "mbarrier.try_wait.parity.acquire.cta.shared::cta.b64 p, [%1], %2;\n\t"    \
        "selp.b32 %0, 1, 0, p;\n\t}"                                               \
        : "=r"(_done) : "r"(_m), "r"(_p) : "memory");                              \
    if (!_done) {                                                                  \
        asm volatile("{\n\t.reg .pred P1;\n\t"                                     \
            "WL_%=:\n\t"                                                           \
            "mbarrier.try_wait.parity.acquire.cta.shared::cta.b64 P1, [%0], %1, 0x989680;\n\t" \
            "@P1 bra.uni WD_%=;\n\t"                                               \
            "bra.uni WL_%=;\n\t"                                                   \
            "WD_%=:\n\t}"                                                          \
            :: "r"(_m), "r"(_p) : "memory");                                       \
    }                                                                              \
} while (0)

#define TMA_LOAD_2D(smem, tm, x, y, mbar) \
    asm volatile("cp.async.bulk.tensor.2d.shared::cta.global.tile.mbarrier::complete_tx::bytes " \
        "[%0], [%1, {%2, %3}], [%4];" \
        :: "r"((uint32_t)(smem)), "l"(tm), "r"((int)(x)), "r"((int)(y)), \
           "r"((uint32_t)(mbar)) : "memory")

#define TC_ALLOC(smem_addr, ncols) \
    asm volatile("tcgen05.alloc.cta_group::1.sync.aligned.shared::cta.b32 [%0], %1;" \
        :: "r"((uint32_t)(smem_addr)), "r"((uint32_t)(ncols)) : "memory")
#define TC_DEALLOC(tmem, ncols) \
    asm volatile("tcgen05.dealloc.cta_group::1.sync.aligned.b32 %0, %1;" \
        :: "r"(tmem), "r"((uint32_t)(ncols)))
#define TC_RELINQ() \
    asm volatile("tcgen05.relinquish_alloc_permit.cta_group::1.sync.aligned;")
#define TC_COMMIT(mbar) \
    asm volatile("tcgen05.commit.cta_group::1.mbarrier::arrive::one.shared::cluster.b64 [%0];" \
        :: "r"((uint32_t)(mbar)) : "memory")
#define TC_FENCE_AFTER()  asm volatile("tcgen05.fence::after_thread_sync;" ::: "memory")
#define TC_WAIT_LD()      asm volatile("tcgen05.wait::ld.sync.aligned;" ::: "memory")

#define TC_LD_X32(r, tmem_addr) \
    asm volatile("tcgen05.ld.sync.aligned.32x32b.x32.b32 " \
        "{%0, %1, %2, %3, %4, %5, %6, %7, %8, %9, %10, %11, %12, %13, %14, %15, " \
        " %16, %17, %18, %19, %20, %21, %22, %23, %24, %25, %26, %27, %28, %29, %30, %31}, [%32];" \
        : "=r"((r)[0]),  "=r"((r)[1]),  "=r"((r)[2]),  "=r"((r)[3]), \
          "=r"((r)[4]),  "=r"((r)[5]),  "=r"((r)[6]),  "=r"((r)[7]), \
          "=r"((r)[8]),  "=r"((r)[9]),  "=r"((r)[10]), "=r"((r)[11]), \
          "=r"((r)[12]), "=r"((r)[13]), "=r"((r)[14]), "=r"((r)[15]), \
          "=r"((r)[16]), "=r"((r)[17]), "=r"((r)[18]), "=r"((r)[19]), \
          "=r"((r)[20]), "=r"((r)[21]), "=r"((r)[22]), "=r"((r)[23]), \
          "=r"((r)[24]), "=r"((r)[25]), "=r"((r)[26]), "=r"((r)[27]), \
          "=r"((r)[28]), "=r"((r)[29]), "=r"((r)[30]), "=r"((r)[31]) \
        : "r"(tmem_addr))

static constexpr uint64_t DESC_BASE_SW128 =
    (uint64_t(2) << 61) | (uint64_t(1) << 46) | (uint64_t(64) << 32) | (uint64_t(1) << 16);
__device__ __forceinline__ uint64_t make_desc(uint32_t addr) {
    return DESC_BASE_SW128 | ((uint64_t)(addr >> 4) & 0x3FFF);
}

__device__ __forceinline__ void mma_f8_ss(uint32_t d, uint64_t ad, uint64_t bd,
                                          uint32_t idesc, bool acc) {
    uint32_t en = acc ? 1u : 0u;
    asm volatile(
        "{\n\t.reg .pred p;\n\t"
        "setp.ne.u32 p, %4, 0;\n\t"
        "tcgen05.mma.cta_group::1.kind::f8f6f4 [%0], %1, %2, %3, {%5, %5, %5, %5}, p;\n\t"
        "}"
        :: "r"(d), "l"(ad), "l"(bd), "r"(idesc), "r"(en), "r"(0u)
        : "memory");
}
// dtype=F32, E4M3, N=128, M=128
#define IDESC_F8 ((1u<<4)|(16u<<17)|(8u<<24))
#endif  // HAS_TCGEN05

// ---------------------------------------------------------------------------
// k_pre: fused pref / spans / wfeat
// ---------------------------------------------------------------------------
__global__ __launch_bounds__(256) void k_pre(
    const int* __restrict__ sent, const int* __restrict__ pos,
    const float* __restrict__ We_wrd, const float* __restrict__ We_pos,
    const float* __restrict__ W_s1)
{
    int bx = blockIdx.x;
    int tid = threadIdx.x;
    if (bx < N_TOK) {
        int i = bx;
        int base = i * N_TOK - (i * (i - 1)) / 2;
        for (int j = i + tid; j < N_TOK; j += 256) {
            int s = base + (j - i);
            g_si[s] = i;
            g_sj[s] = j;
        }
        if (bx == 0) {
            for (int s = NSPAN + tid; s < NSPAN_PAD; s += 256) {
                g_si[s] = 0; g_sj[s] = 0;
            }
        }
    } else if (bx < N_TOK + 4) {
        int c = (bx - N_TOK) * 256 + tid;
        bool isPos = (c < WDIM);
        const float* base = isPos ? (We_pos + c) : (We_wrd + (c - WDIM));
        const int*   idx  = isPos ? pos : sent;
        float run = 0.f;
        g_pref[c] = 0.f;
        #pragma unroll 4
        for (int t = 0; t < N_TOK; ++t) {
            run += base[(size_t)idx[t] * WDIM];
            g_pref[(t + 1) * EMB + c] = run;
        }
    } else {
        int n = (bx - N_TOK - 4) * 256 + tid;
        float sl = 0.f, si = 0.f, se = 0.f;
        #pragma unroll
        for (int r = 0; r < 16; ++r) {
            sl += W_s1[(HDIM +      r) * HDIM + n];
            si += W_s1[(HDIM + 16 + r) * HDIM + n];
            se += W_s1[(HDIM + 32 + r) * HDIM + n];
        }
        g_wf[n] = sl; g_wf[HDIM + n] = si; g_wf[2 * HDIM + n] = se;
    }
}

// ---------------------------------------------------------------------------
// k_gemmP: P = pref @ W_dan1  (64x64 tiles, 4x4/thread) fp32 -> bf16
// ---------------------------------------------------------------------------
__global__ __launch_bounds__(256) void k_gemmP(const float* __restrict__ W)
{
    __shared__ float As[64][17];
    __shared__ float Bs[16][68];
    int tid = threadIdx.x;
    int tx = tid % 16, ty = tid / 16;
    int m0 = blockIdx.x * 64, n0 = blockIdx.y * 64;
    float acc[4][4] = {};

    for (int kk = 0; kk < EMB; kk += 16) {
        #pragma unroll
        for (int e = tid; e < 64 * 16; e += 256) {
            int r = e >> 4, c = e & 15;
            int gm = m0 + r;
            As[r][c] = (gm <= N_TOK) ? g_pref[gm * EMB + kk + c] : 0.f;
        }
        #pragma unroll
        for (int e = tid; e < 16 * 64; e += 256) {
            int r = e >> 6, c = e & 63;
            Bs[r][c] = W[(kk + r) * HDIM + n0 + c];
        }
        __syncthreads();
        #pragma unroll
        for (int k = 0; k < 16; ++k) {
            float a[4], b[4];
            #pragma unroll
            for (int q = 0; q < 4; ++q) { a[q] = As[ty * 4 + q][k]; b[q] = Bs[k][tx * 4 + q]; }
            #pragma unroll
            for (int i = 0; i < 4; ++i)
                #pragma unroll
                for (int j = 0; j < 4; ++j)
                    acc[i][j] = fmaf(a[i], b[j], acc[i][j]);
        }
        __syncthreads();
    }
    #pragma unroll
    for (int i = 0; i < 4; ++i) {
        int gm = m0 + ty * 4 + i;
        if (gm <= N_TOK)
            #pragma unroll
            for (int j = 0; j < 4; ++j)
                g_Pb[gm * HDIM + n0 + tx * 4 + j] = __float2bfloat16(acc[i][j]);
    }
}

// ---------------------------------------------------------------------------
// k_mid: h1 materialization (e4m3 x2^8, bf16 P reads) + weight transposes
// ---------------------------------------------------------------------------
__device__ __forceinline__ void transp_body(const float* __restrict__ src,
                                            uint8_t* __restrict__ dst, int q, int tid)
{
    __shared__ float t[32][33];
    int tx = tid & 31, ty = tid >> 5;
    int bx = q & 31, by = q >> 5;
    int x = bx * 32 + tx;
    int y = by * 32 + ty;
    #pragma unroll
    for (int j = 0; j < 32; j += 8)
        t[ty + j][tx] = src[(size_t)(y + j) * HDIM + x];
    __syncthreads();
    x = by * 32 + tx;
    y = bx * 32 + ty;
    #pragma unroll
    for (int j = 0; j < 32; j += 8) {
        __nv_fp8_e4m3 v(t[tx][ty + j] * W_SCALE);
        dst[(size_t)(y + j) * HDIM + x] = *reinterpret_cast<uint8_t*>(&v);
    }
}

__global__ __launch_bounds__(256) void k_mid(const float* __restrict__ b_dan1,
                                             const float* __restrict__ W_dan2,
                                             const float* __restrict__ W_s1)
{
    int bx = blockIdx.x;
    int tid = threadIdx.x;
    if (bx < NSPAN_PAD / 16) {
        int s = bx * 16 + (tid >> 4);
        int sc = (s < NSPAN) ? s : (NSPAN - 1);
        int i_ = g_si[sc], j_ = g_sj[sc];
        float inv = 1.0f / (float)(j_ - i_ + 1);
        const __nv_bfloat16* pe = g_Pb + (size_t)(j_ + 1) * HDIM;
        const __nv_bfloat16* pi = g_Pb + (size_t)i_ * HDIM;
        int cg = (tid & 15) * 64;
        uint8_t* orow = g_h1f8 + (size_t)s * HDIM + cg;
        #pragma unroll
        for (int q = 0; q < 64; q += 16) {
            uint4 e0 = *(const uint4*)(pe + cg + q);
            uint4 e1 = *(const uint4*)(pe + cg + q + 8);
            uint4 i0 = *(const uint4*)(pi + cg + q);
            uint4 i1 = *(const uint4*)(pi + cg + q + 8);
            uint32_t ew[8] = {e0.x, e0.y, e0.z, e0.w, e1.x, e1.y, e1.z, e1.w};
            uint32_t iw[8] = {i0.x, i0.y, i0.z, i0.w, i1.x, i1.y, i1.z, i1.w};
            uint32_t w[4];
            #pragma unroll
            for (int g = 0; g < 4; ++g) {
                float2 ea = bf2_to_f2(ew[g * 2]);
                float2 eb = bf2_to_f2(ew[g * 2 + 1]);
                float2 ia = bf2_to_f2(iw[g * 2]);
                float2 ib = bf2_to_f2(iw[g * 2 + 1]);
                float4 b4 = *(const float4*)(b_dan1 + cg + q + g * 4);
                float v0 = fmaxf(fmaf(ea.x - ia.x, inv, b4.x), 0.f) * H_SCALE;
                float v1 = fmaxf(fmaf(ea.y - ia.y, inv, b4.y), 0.f) * H_SCALE;
                float v2 = fmaxf(fmaf(eb.x - ib.x, inv, b4.z), 0.f) * H_SCALE;
                float v3 = fmaxf(fmaf(eb.y - ib.y, inv, b4.w), 0.f) * H_SCALE;
                w[g] = pack_e4m3x2(v0, v1) | (pack_e4m3x2(v2, v3) << 16);
            }
            uint4 o; o.x = w[0]; o.y = w[1]; o.z = w[2]; o.w = w[3];
            *(uint4*)(orow + q) = o;
        }
    } else if (bx < NSPAN_PAD / 16 + 1024) {
        transp_body(W_dan2, g_Wt2f8, bx - NSPAN_PAD / 16, tid);
    } else {
        transp_body(W_s1, g_Ws1tf8, bx - NSPAN_PAD / 16 - 1024, tid);
    }
}

// ---------------------------------------------------------------------------
// Big GEMM, 128x256 tile, K=1024 (plain fp8 tcgen05 + TMA / fp32 fallback).
// Grid (4, MTILES), 2 CTAs/SM (TMEM 256 cols each). 2-stage ring.
// Split producer: thread 0 = MMA issuer; thread 32 = TMA issuer.
// TMA prologue issued BEFORE tcgen05.alloc (warp 1 runs while warp 0 allocs).
// ---------------------------------------------------------------------------
template <int MODE>
__global__ __launch_bounds__(256, 2)
void k_gemm_big(const __grid_constant__ CUtensorMap tmA,
                const __grid_constant__ CUtensorMap tmB,
                const float* __restrict__ W,          // fp32 [K][N] (fallback)
                const float* __restrict__ bias2,      // b_dan2 / b_s1
                const float* __restrict__ Ws2)        // MODE 3
{
#if HAS_TCGEN05
    extern __shared__ __align__(1024) char dyn[];
    // stage st: A @ st*49152 (16KB), B @ st*49152+16384 (32KB)
    char* sA[2] = { dyn,          dyn + 49152 };
    char* sB[2] = { dyn + 16384,  dyn + 65536 };

    __shared__ float sepi[5 * 256];
    __shared__ float s_red[256];
    __shared__ __align__(8) unsigned long long s_mbar[5];  // full0,full1,done0,done1,final
    __shared__ uint32_t s_tmemptr;

    const int tid = threadIdx.x;
    const int m0 = blockIdx.y * 128, n0 = blockIdx.x * 256;

    if (tid == 0) {
        MBAR_INIT(smem_u32(&s_mbar[0]), 1);
        MBAR_INIT(smem_u32(&s_mbar[1]), 1);
        MBAR_INIT(smem_u32(&s_mbar[2]), 1);
        MBAR_INIT(smem_u32(&s_mbar[3]), 1);
        MBAR_INIT(smem_u32(&s_mbar[4]), 1);
    }
    if (MODE == 2) {
        if (tid < 256) sepi[tid] = bias2[n0 + tid];
    } else {
        sepi[tid]        = bias2[n0 + tid];
        sepi[256 + tid]  = g_wf[n0 + tid];
        sepi[512 + tid]  = g_wf[HDIM + n0 + tid];
        sepi[768 + tid]  = g_wf[2 * HDIM + n0 + tid];
        sepi[1024 + tid] = Ws2[n0 + tid];
    }
    __syncthreads();

    // ---- warp 1: TMA prologue (chunks 0,1) fires while warp 0 allocs TMEM
    if (tid == 32) {
        const uint32_t fullb[2] = { smem_u32(&s_mbar[0]), smem_u32(&s_mbar[1]) };
        #pragma unroll
        for (int st = 0; st < 2; ++st) {
            MBAR_EXPECT_TX(fullb[st], 49152);
            TMA_LOAD_2D(smem_u32(sA[st]), &tmA, st * 128, m0, fullb[st]);
            TMA_LOAD_2D(smem_u32(sB[st]), &tmB, st * 128, n0, fullb[st]);
        }
    }
    if (tid < 32) {
        TC_ALLOC(smem_u32(&s_tmemptr), 256);
        TC_RELINQ();
    }
    __syncthreads();
    const uint32_t tmem = s_tmemptr;

    if (tid == 0) {
        // ---------------- MMA issuer ----------------
        const uint32_t fullb[2] = { smem_u32(&s_mbar[0]), smem_u32(&s_mbar[1]) };
        const uint32_t doneb[2] = { smem_u32(&s_mbar[2]), smem_u32(&s_mbar[3]) };
        const uint32_t finb     = smem_u32(&s_mbar[4]);
        const uint64_t adesc[2] = { make_desc(smem_u32(sA[0])), make_desc(smem_u32(sA[1])) };
        const uint64_t bdesc[2] = { make_desc(smem_u32(sB[0])), make_desc(smem_u32(sB[1])) };

        int fph[2] = {0, 0};
        #pragma unroll 1
        for (int c = 0; c < 8; ++c) {
            const int st = c & 1;
            MBAR_WAIT_PARITY(fullb[st], fph[st]); fph[st] ^= 1;
            #pragma unroll
            for (int stp = 0; stp < 4; ++stp) {
                bool acc = (c > 0) || (stp > 0);
                mma_f8_ss(tmem,       adesc[st] + stp * 2, bdesc[st] + stp * 2,        IDESC_F8, acc);
                mma_f8_ss(tmem + 128, adesc[st] + stp * 2, bdesc[st] + 1024 + stp * 2, IDESC_F8, acc);
            }
            TC_COMMIT(doneb[st]);
        }
        TC_COMMIT(finb);   // arrives when ALL prior MMAs complete
    } else if (tid == 32) {
        // ---------------- TMA issuer: reissue chunks 2..7 ----------------
        const uint32_t fullb[2] = { smem_u32(&s_mbar[0]), smem_u32(&s_mbar[1]) };
        const uint32_t doneb[2] = { smem_u32(&s_mbar[2]), smem_u32(&s_mbar[3]) };
        int dph[2] = {0, 0};
        #pragma unroll 1
        for (int c = 0; c < 6; ++c) {
            const int st = c & 1;
            MBAR_WAIT_PARITY(doneb[st], dph[st]); dph[st] ^= 1;
            MBAR_EXPECT_TX(fullb[st], 49152);
            TMA_LOAD_2D(smem_u32(sA[st]), &tmA, (c + 2) * 128, m0, fullb[st]);
            TMA_LOAD_2D(smem_u32(sB[st]), &tmB, (c + 2) * 128, n0, fullb[st]);
        }
    }

    // all threads: wait for the final commit (phase 0), then read TMEM
    MBAR_WAIT_PARITY(smem_u32(&s_mbar[4]), 0);
    TC_FENCE_AFTER();

    // ---- epilogue: all 8 warps. wg0 -> cols 0..127, wg1 -> 128..255.
    {
        const int wg = tid >> 7;
        const int rt = tid & 127;
        const int gs = m0 + rt;
        if (MODE == 2) {
            bool ok = gs < NSPAN;
            uint8_t* orow = g_h2f8 + (size_t)(ok ? gs : 0) * HDIM + n0 + wg * 128;
            #pragma unroll 1
            for (int nb = 0; nb < 4; ++nb) {
                uint32_t r[32];
                TC_LD_X32(r, tmem + wg * 128 + nb * 32);
                TC_WAIT_LD();
                if (ok) {
                    int cb0 = wg * 128 + nb * 32;
                    uint32_t w[8];
                    #pragma unroll
                    for (int q = 0; q < 32; q += 4) {
                        float a0 = fmaxf(fmaf(__uint_as_float(r[q + 0]), DESCALE, sepi[cb0 + q + 0]), 0.f) * H_SCALE;
                        float a1 = fmaxf(fmaf(__uint_as_float(r[q + 1]), DESCALE, sepi[cb0 + q + 1]), 0.f) * H_SCALE;
                        float a2 = fmaxf(fmaf(__uint_as_float(r[q + 2]), DESCALE, sepi[cb0 + q + 2]), 0.f) * H_SCALE;
                        float a3 = fmaxf(fmaf(__uint_as_float(r[q + 3]), DESCALE, sepi[cb0 + q + 3]), 0.f) * H_SCALE;
                        w[q >> 2] = pack_e4m3x2(a0, a1) | (pack_e4m3x2(a2, a3) << 16);
                    }
                    uint4 o;
                    o.x = w[0]; o.y = w[1]; o.z = w[2]; o.w = w[3];
                    *(uint4*)(orow + nb * 32) = o;
                    o.x = w[4]; o.y = w[5]; o.z = w[6]; o.w = w[7];
                    *(uint4*)(orow + nb * 32 + 16) = o;
                }
            }
        } else {
            int sc = (gs < NSPAN) ? gs : (NSPAN - 1);
            int i_ = g_si[sc], j_ = g_sj[sc];
            float fl = (float)(j_ - i_ + 1);
            float fi = (float)i_;
            float fe = (float)(j_ + 1);
            float sum = 0.f;
            #pragma unroll 1
            for (int nb = 0; nb < 4; ++nb) {
                uint32_t r[32];
                TC_LD_X32(r, tmem + wg * 128 + nb * 32);
                TC_WAIT_LD();
                #pragma unroll
                for (int q = 0; q < 32; ++q) {
                    int n = wg * 128 + nb * 32 + q;
                    float v = fmaf(__uint_as_float(r[q]), DESCALE, sepi[n]);
                    v = fmaf(fl, sepi[256 + n], v);
                    v = fmaf(fi, sepi[512 + n], v);
                    v = fmaf(fe, sepi[768 + n], v);
                    v = fmaxf(v, 0.f);
                    sum = fmaf(v, sepi[1024 + n], sum);
                }
            }
            s_red[tid] = sum;
            __syncthreads();
            if (tid < 128)
                g_part[(size_t)blockIdx.x * NSPAN_PAD + m0 + tid] = s_red[tid] + s_red[tid + 128];
        }
    }
    __syncthreads();
    if (tid == 0) {
        #pragma unroll
        for (int q = 0; q < 5; ++q) MBAR_INVAL(smem_u32(&s_mbar[q]));
    }
    __syncthreads();
    if (tid < 32) TC_DEALLOC(tmem, 256);

#else
    // ======================= SIMT fp32 fallback (two 128-wide halves) ==========
    __shared__ __align__(16) float sh[2304];
    float* As = sh;
    float* Bs = sh + 1024;

    int tid = threadIdx.x;
    int tx = tid % 16, ty = tid / 16;
    int m0 = blockIdx.y * 128;
    const uint8_t* Af8 = (MODE == 2) ? g_h1f8 : g_h2f8;

    int lm = tid >> 1, lkh = tid & 1;
    int sA_ = m0 + lm; if (sA_ >= NSPAN) sA_ = NSPAN - 1;

    int br = tid >> 5;
    int bc = (tid & 31) << 2;

    float rs_tot[8] = {};

    #pragma unroll 1
    for (int nh = 0; nh < 2; ++nh) {
        int n0 = blockIdx.x * 256 + nh * 128;

        float acc[8][8];
        #pragma unroll
        for (int a = 0; a < 8; ++a)
            #pragma unroll
            for (int b = 0; b < 8; ++b) acc[a][b] = 0.f;

        for (int kk = 0; kk < HDIM; kk += 8) {
            const uint8_t* ar = Af8 + (size_t)sA_ * HDIM + kk + lkh * 4;
            #pragma unroll
            for (int q = 0; q < 4; ++q) {
                __nv_fp8_e4m3 f8 = *reinterpret_cast<const __nv_fp8_e4m3*>(ar + q);
                As[(lkh * 4 + q) * 128 + lm] = float(f8) * H_INV;
            }
            *(float4*)(Bs + br * 128 + bc) = *(const float4*)(W + (size_t)(kk + br) * HDIM + n0 + bc);
            __syncthreads();

            #pragma unroll
            for (int k = 0; k < 8; ++k) {
                float a[8], b[8];
                float4 t;
                t = *(const float4*)(As + k * 128 + (ty << 2));      a[0]=t.x; a[1]=t.y; a[2]=t.z; a[3]=t.w;
                t = *(const float4*)(As + k * 128 + (ty << 2) + 64); a[4]=t.x; a[5]=t.y; a[6]=t.z; a[7]=t.w;
                t = *(const float4*)(Bs + k * 128 + (tx << 2));      b[0]=t.x; b[1]=t.y; b[2]=t.z; b[3]=t.w;
                t = *(const float4*)(Bs + k * 128 + (tx << 2) + 64); b[4]=t.x; b[5]=t.y; b[6]=t.z; b[7]=t.w;
                #pragma unroll
                for (int ii = 0; ii < 8; ++ii)
                    #pragma unroll
                    for (int jj = 0; jj < 8; ++jj)
                        acc[ii][jj] = fmaf(a[ii], b[jj], acc[ii][jj]);
            }
            __syncthreads();
        }

        if (MODE == 2) {
            float cb[8];
            #pragma unroll
            for (int q = 0; q < 4; ++q) {
                cb[q]     = bias2[n0 + (tx << 2) + q];
                cb[4 + q] = bias2[n0 + (tx << 2) + 64 + q];
            }
            #pragma unroll
            for (int ri = 0; ri < 8; ++ri) {
                int r = (ri < 4) ? ((ty << 2) + ri) : (64 + (ty << 2) + ri - 4);
                int gs = m0 + r;
                if (gs < NSPAN) {
                    #pragma unroll
                    for (int q = 0; q < 4; ++q) {
                        __nv_fp8_e4m3 v0(fmaxf(acc[ri][q] + cb[q], 0.f) * H_SCALE);
                        __nv_fp8_e4m3 v1(fmaxf(acc[ri][4 + q] + cb[4 + q], 0.f) * H_SCALE);
                        g_h2f8[(size_t)gs * HDIM + n0 + (tx << 2) + q]      = *reinterpret_cast<uint8_t*>(&v0);
                        g_h2f8[(size_t)gs * HDIM + n0 + (tx << 2) + 64 + q] = *reinterpret_cast<uint8_t*>(&v1);
                    }
                }
            }
        } else {
            int cbase = n0 + (tx << 2);
            float cb[8], cl[8], ci[8], ce[8], cw[8];
            #pragma unroll
            for (int q = 0; q < 4; ++q) {
                int c0 = cbase + q, c1 = cbase + 64 + q;
                cb[q] = bias2[c0];             cb[4+q] = bias2[c1];
                cl[q] = g_wf[c0];              cl[4+q] = g_wf[c1];
                ci[q] = g_wf[HDIM + c0];       ci[4+q] = g_wf[HDIM + c1];
                ce[q] = g_wf[2*HDIM + c0];     ce[4+q] = g_wf[2*HDIM + c1];
                cw[q] = Ws2[c0];               cw[4+q] = Ws2[c1];
            }
            #pragma unroll
            for (int ri = 0; ri < 8; ++ri) {
                int r = (ri < 4) ? ((ty << 2) + ri) : (64 + (ty << 2) + ri - 4);
                int gs = m0 + r; int sc = (gs < NSPAN) ? gs : (NSPAN - 1);
                int ii_ = g_si[sc], jj_ = g_sj[sc];
                float fl = (float)(jj_ - ii_ + 1);
                float fi = (float)ii_;
                float fe = (float)(jj_ + 1);
                float sum = 0.f;
                #pragma unroll
                for (int cc = 0; cc < 8; ++cc) {
                    float v = acc[ri][cc] + cb[cc];
                    v = fmaf(fl, cl[cc], v);
                    v = fmaf(fi, ci[cc], v);
                    v = fmaf(fe, ce[cc], v);
                    v = fmaxf(v, 0.f);
                    sum = fmaf(v, cw[cc], sum);
                }
                rs_tot[ri] += sum;
            }
        }
    }

    if (MODE == 3) {
        #pragma unroll
        for (int ri = 0; ri < 8; ++ri) {
            int r = (ri < 4) ? ((ty << 2) + ri) : (64 + (ty << 2) + ri - 4);
            sh[r * 17 + tx] = rs_tot[ri];
        }
        __syncthreads();
        if (tid < 128) {
            float t = 0.f;
            #pragma unroll
            for (int q = 0; q < 16; ++q) t += sh[tid * 17 + q];
            g_part[(size_t)blockIdx.x * NSPAN_PAD + m0 + tid] = t;
        }
    }
#endif
}

// ---------------------------------------------------------------------------
// Final reduce (4 column-block partials)
// ---------------------------------------------------------------------------
__global__ void k_final(const float* __restrict__ b_s2, float* __restrict__ out)
{
    int s = blockIdx.x * blockDim.x + threadIdx.x;
    if (s < NSPAN) {
        float t = b_s2[0];
        #pragma unroll
        for (int q = 0; q < 4; ++q) t += g_part[(size_t)q * NSPAN_PAD + s];
        out[s] = t;
    }
}

// ---------------------------------------------------------------------------
// Host: tensor maps
// ---------------------------------------------------------------------------
typedef CUresult (*tm_encode_fn)(
    CUtensorMap*, CUtensorMapDataType, cuuint32_t, void*,
    const cuuint64_t*, const cuuint64_t*, const cuuint32_t*, const cuuint32_t*,
    CUtensorMapInterleave, CUtensorMapSwizzle, CUtensorMapL2promotion,
    CUtensorMapFloatOOBfill);

static tm_encode_fn get_encoder()
{
    static tm_encode_fn fn = nullptr;
    if (!fn) {
        cudaDriverEntryPointQueryResult st;
        void* p = nullptr;
        cudaGetDriverEntryPointByVersion("cuTensorMapEncodeTiled", &p, 12000,
                                         cudaEnableDefault, &st);
        fn = (tm_encode_fn)p;
    }
    return fn;
}

static void make_tm_2d(CUtensorMap* tm, void* base, uint64_t rows, uint32_t box_rows)
{
    cuuint64_t dims[2]    = { (cuuint64_t)HDIM, (cuuint64_t)rows };
    cuuint64_t strides[1] = { (cuuint64_t)HDIM };
    cuuint32_t box[2]     = { 128u, box_rows };
    cuuint32_t es[2]      = { 1u, 1u };
    get_encoder()(tm, CU_TENSOR_MAP_DATA_TYPE_UINT8, 2, base,
                  dims, strides, box, es,
                  CU_TENSOR_MAP_INTERLEAVE_NONE, CU_TENSOR_MAP_SWIZZLE_128B,
                  CU_TENSOR_MAP_L2_PROMOTION_L2_128B,
                  CU_TENSOR_MAP_FLOAT_OOB_FILL_NONE);
}

extern "C" void kernel_launch(void* const* d_in, const int* in_sizes, int n_in,
                              void* d_out, int out_size)
{
    const int*   sent    = (const int*)d_in[0];
    const int*   pos     = (const int*)d_in[1];
    const float* We_wrd  = (const float*)d_in[2];
    const float* We_pos  = (const float*)d_in[3];
    const float* W_dan1  = (const float*)d_in[4];
    const float* b_dan1  = (const float*)d_in[5];
    const float* W_dan2  = (const float*)d_in[6];
    const float* b_dan2  = (const float*)d_in[7];
    const float* W_s1    = (const float*)d_in[8];
    const float* b_s1    = (const float*)d_in[9];
    const float* W_s2    = (const float*)d_in[10];
    const float* b_s2    = (const float*)d_in[11];
    float* out = (float*)d_out;

    static bool init_done = false;
    static CUtensorMap tmA2, tmB2, tmA3, tmB3;
    if (!init_done) {
        cudaFuncSetAttribute((const void*)k_gemm_big<2>,
                             cudaFuncAttributeMaxDynamicSharedMemorySize, 98304);
        cudaFuncSetAttribute((const void*)k_gemm_big<3>,
                             cudaFuncAttributeMaxDynamicSharedMemorySize, 98304);
        void *h1p, *h2p, *wt2p, *ws1p;
        cudaGetSymbolAddress(&h1p,  g_h1f8);
        cudaGetSymbolAddress(&h2p,  g_h2f8);
        cudaGetSymbolAddress(&wt2p, g_Wt2f8);
        cudaGetSymbolAddress(&ws1p, g_Ws1tf8);
        make_tm_2d(&tmA2, h1p,  NSPAN_PAD, 128);
        make_tm_2d(&tmA3, h2p,  NSPAN_PAD, 128);
        make_tm_2d(&tmB2, wt2p, HDIM,      256);
        make_tm_2d(&tmB3, ws1p, HDIM,      256);
        init_done = true;
    }

    k_pre  <<<N_TOK + 8, 256>>>(sent, pos, We_wrd, We_pos, W_s1);          // 0
    k_gemmP<<<dim3(7, 16), 256>>>(W_dan1);                                  // 1
    k_mid  <<<NSPAN_PAD / 16 + 2048, 256>>>(b_dan1, W_dan2, W_s1);          // 2
    k_gemm_big<2><<<dim3(4, MTILES), 256, 98304>>>(tmA2, tmB2, W_dan2, b_dan2, nullptr);  // 3 (ncu slot)
    k_gemm_big<3><<<dim3(4, MTILES), 256, 98304>>>(tmA3, tmB3, W_s1,   b_s1,  W_s2);      // 4
    k_final<<<(NSPAN + 255) / 256, 256>>>(b_s2, out);                       // 5
}